// round 5
// baseline (speedup 1.0000x reference)
#include <cuda_runtime.h>
#include <cuda_bf16.h>

// ChannelPruner: out[b,o,h,w] = sum_c w[o,c] * x[b,c,h,w]
// x: (32, 256, 56, 56) fp32; w: (256,256,1,1) fp32, sparse rows discovered at
// runtime (correct for ANY w).
//
// R5: R2 block shape (8192 blocks = one (b,o) plane each, 256 thr, MLP-4) but
// with a fully warp-autonomous prologue: NO shared memory, NO __syncthreads.
// Each warp scans the w row in 8 coalesced 32-lane chunks (L1-hot, 1KB row),
// ballots nonzeros, and shfl-broadcasts (c, v). Warps never wait on each
// other, so the SM always has load bursts in flight. Streaming stores keep
// x L2-resident across graph replays.

#define N_CH    256
#define BATCH   32
#define HW4     784                   // (56*56)/4 float4 per plane
#define BSTRIDE (N_CH * HW4)
#define NBLK    (BATCH * N_CH)        // 8192

__global__ __launch_bounds__(256, 6) void prune_fused(const float4* __restrict__ x,
                                                      const float*  __restrict__ w,
                                                      float4* __restrict__ out) {
    const int tid  = threadIdx.x;
    const int lane = tid & 31;

    const int bo = blockIdx.x;            // plane index b*256 + o
    const int o  = bo & (N_CH - 1);

    const float* wr = w + o * N_CH;
    const float4* xb = x + (size_t)(bo >> 8) * BSTRIDE;
    const bool tail = tid < (HW4 - 768);  // tid < 16

    float4 z = make_float4(0.f, 0.f, 0.f, 0.f);
    float4 a0 = z, a1 = z, a2 = z, a3 = z;

    // Warp-autonomous sparse row scan: 8 chunks of 32 channels.
#pragma unroll
    for (int ch = 0; ch < N_CH; ch += 32) {
        const float wv = __ldg(wr + ch + lane);          // coalesced, L1-hot
        unsigned m = __ballot_sync(0xffffffffu, wv != 0.0f);
        while (m) {
            const int l = __ffs(m) - 1;
            m &= m - 1;
            const float v = __shfl_sync(0xffffffffu, wv, l);
            const int   c = ch + l;

            const float4* xc = xb + (size_t)c * HW4 + tid;
            // 4 independent LDG.128 (MLP=4) before any FMA
            const float4 r0 = __ldg(xc);
            const float4 r1 = __ldg(xc + 256);
            const float4 r2 = __ldg(xc + 512);
            float4 r3 = z;
            if (tail) r3 = __ldg(xc + 768);

            a0.x += v * r0.x; a0.y += v * r0.y; a0.z += v * r0.z; a0.w += v * r0.w;
            a1.x += v * r1.x; a1.y += v * r1.y; a1.z += v * r1.z; a1.w += v * r1.w;
            a2.x += v * r2.x; a2.y += v * r2.y; a2.z += v * r2.z; a2.w += v * r2.w;
            if (tail) {
                a3.x += v * r3.x; a3.y += v * r3.y; a3.z += v * r3.z; a3.w += v * r3.w;
            }
        }
    }

    float4* ob = out + (size_t)bo * HW4 + tid;
    __stcs(ob,       a0);
    __stcs(ob + 256, a1);
    __stcs(ob + 512, a2);
    if (tail) __stcs(ob + 768, a3);
}

extern "C" void kernel_launch(void* const* d_in, const int* in_sizes, int n_in,
                              void* d_out, int out_size) {
    const float4* x = (const float4*)d_in[0];
    const float*  w = (const float*)d_in[1];
    float4* out = (float4*)d_out;

    prune_fused<<<NBLK, 256>>>(x, w, out);
}

// round 6
// speedup vs baseline: 1.1889x; 1.1889x over previous
#include <cuda_runtime.h>
#include <cuda_bf16.h>

// ChannelPruner: out[b,o,h,w] = sum_c w[o,c] * x[b,c,h,w]
// x: (32, 256, 56, 56) fp32; w: (256,256,1,1) fp32, sparse rows discovered at
// runtime (correct for ANY w).
//
// R6 = R2's proven body (8192 one-plane blocks, MLP-4, plain stores, 32 regs)
// with the prologue moved into a ~0.3us build_csr pre-kernel. The apply kernel
// has NO smem / NO barriers: metadata is 2-3 L1-broadcast scalar loads, so
// every warp reaches its x-load burst in ~60 cyc -> high load duty cycle.

#define N_CH    256
#define BATCH   32
#define HW4     784                   // (56*56)/4 float4 per plane
#define BSTRIDE (N_CH * HW4)
#define NBLK    (BATCH * N_CH)        // 8192

// Per-row compacted CSR (fully overwritten each launch; graph-replay safe).
__device__ int   g_nnz[N_CH];
__device__ int   g_cols[N_CH * N_CH];
__device__ float g_vals[N_CH * N_CH];

// ---------------------------------------------------------------------------
// Kernel 1: one warp per weight row, compact nonzeros via warp scan. (~0.3us)
// ---------------------------------------------------------------------------
__global__ __launch_bounds__(256) void build_csr(const float* __restrict__ w) {
    const int row  = blockIdx.x * 8 + (threadIdx.x >> 5);
    const int lane = threadIdx.x & 31;
    const float* wr = w + row * N_CH;

    float v[8];
    int cnt = 0;
    const int base = lane * 8;
#pragma unroll
    for (int k = 0; k < 8; k++) {
        v[k] = wr[base + k];
        if (v[k] != 0.0f) cnt++;
    }

    int scan = cnt;                               // inclusive warp scan
#pragma unroll
    for (int d = 1; d < 32; d <<= 1) {
        int t = __shfl_up_sync(0xffffffffu, scan, d);
        if (lane >= d) scan += t;
    }
    const int total = __shfl_sync(0xffffffffu, scan, 31);
    int p = row * N_CH + (scan - cnt);
#pragma unroll
    for (int k = 0; k < 8; k++) {
        if (v[k] != 0.0f) { g_cols[p] = base + k; g_vals[p] = v[k]; p++; }
    }
    if (lane == 31) g_nnz[row] = total;
}

// ---------------------------------------------------------------------------
// Kernel 2: one (b,o) plane per block, 4 float4 outputs per thread, MLP-4.
// No smem, no barriers — metadata via L1-broadcast scalar loads.
// ---------------------------------------------------------------------------
__global__ __launch_bounds__(256, 8) void apply_csr(const float4* __restrict__ x,
                                                    float4* __restrict__ out) {
    const int tid = threadIdx.x;
    const int bo  = blockIdx.x;
    const int o   = bo & (N_CH - 1);

    const int nnz = __ldg(&g_nnz[o]);
    const int rb  = o * N_CH;

    const float4* xb = x + (size_t)(bo >> 8) * BSTRIDE;
    const bool tail = tid < (HW4 - 768);          // tid < 16

    float4 z = make_float4(0.f, 0.f, 0.f, 0.f);
    float4 a0 = z, a1 = z, a2 = z, a3 = z;

#pragma unroll 1
    for (int j = 0; j < nnz; j++) {
        const int   c = __ldg(&g_cols[rb + j]);   // uniform, L1-broadcast
        const float v = __ldg(&g_vals[rb + j]);

        const float4* xc = xb + (size_t)c * HW4 + tid;
        const float4 r0 = __ldg(xc);
        const float4 r1 = __ldg(xc + 256);
        const float4 r2 = __ldg(xc + 512);
        float4 r3 = z;
        if (tail) r3 = __ldg(xc + 768);

        a0.x += v * r0.x; a0.y += v * r0.y; a0.z += v * r0.z; a0.w += v * r0.w;
        a1.x += v * r1.x; a1.y += v * r1.y; a1.z += v * r1.z; a1.w += v * r1.w;
        a2.x += v * r2.x; a2.y += v * r2.y; a2.z += v * r2.z; a2.w += v * r2.w;
        if (tail) {
            a3.x += v * r3.x; a3.y += v * r3.y; a3.z += v * r3.z; a3.w += v * r3.w;
        }
    }

    float4* ob = out + (size_t)bo * HW4 + tid;
    ob[0]   = a0;
    ob[256] = a1;
    ob[512] = a2;
    if (tail) ob[768] = a3;
}

extern "C" void kernel_launch(void* const* d_in, const int* in_sizes, int n_in,
                              void* d_out, int out_size) {
    const float4* x = (const float4*)d_in[0];
    const float*  w = (const float*)d_in[1];
    float4* out = (float4*)d_out;

    build_csr<<<32, 256>>>(w);
    apply_csr<<<NBLK, 256>>>(x, out);
}

// round 7
// speedup vs baseline: 1.2684x; 1.0669x over previous
#include <cuda_runtime.h>
#include <cuda_bf16.h>

// ChannelPruner: out[b,o,h,w] = sum_c w[o,c] * x[b,c,h,w]
// x: (32, 256, 56, 56) fp32; w: (256,256,1,1) fp32, sparse rows discovered at
// runtime (correct for ANY w).
//
// R7 = R2 (best kernel so far: fused single launch, 8192 one-plane blocks,
// 256 thr, MLP-4 load bursts, 32 regs / occ ~80%) with ONE isolated change:
// __stcs (evict-first) on the output stores, so the 103 MB write stream does
// not evict the L2-resident x array (x=103MB vs L2=126MB). Across graph
// replays this should push the residual ~22MB of DRAM x-reads into L2.

#define N_CH   256
#define BATCH  32
#define HW4    784                    // (56*56)/4 float4 per plane
#define NPLANE (BATCH * N_CH)         // 8192 blocks

__global__ __launch_bounds__(256, 8) void prune_fused(const float4* __restrict__ x,
                                                      const float*  __restrict__ w,
                                                      float4* __restrict__ out) {
    __shared__ int   s_cols[N_CH];
    __shared__ float s_vals[N_CH];
    __shared__ int   s_warp_off[9];

    const int tid  = threadIdx.x;
    const int lane = tid & 31;
    const int wid  = tid >> 5;

    const int bo = blockIdx.x;        // plane index b*256 + o
    const int o  = bo & (N_CH - 1);

    // ---- prologue: deterministic compaction of w row o ----
    const float wv = __ldg(&w[o * N_CH + tid]);
    const unsigned mask = __ballot_sync(0xffffffffu, wv != 0.0f);
    if (lane == 0) s_warp_off[wid + 1] = __popc(mask);
    __syncthreads();
    if (tid == 0) {
        int acc = 0;
        s_warp_off[0] = 0;
#pragma unroll
        for (int i = 0; i < 8; i++) { acc += s_warp_off[i + 1]; s_warp_off[i + 1] = acc; }
    }
    __syncthreads();
    if (wv != 0.0f) {
        const int pos = s_warp_off[wid] + __popc(mask & ((1u << lane) - 1u));
        s_cols[pos] = tid;
        s_vals[pos] = wv;
    }
    __syncthreads();

    const int nnz = s_warp_off[8];

    // ---- body: 4 float4 outputs per thread, idx = tid + k*256 ----
    float4 z = make_float4(0.f, 0.f, 0.f, 0.f);
    float4 a0 = z, a1 = z, a2 = z, a3 = z;

    const float4* xb = x + (size_t)(bo >> 8) * (N_CH * HW4);   // batch base
    const bool tail = tid < (HW4 - 768);                        // tid < 16

    for (int j = 0; j < nnz; j++) {
        const int   c = s_cols[j];
        const float v = s_vals[j];
        const float4* xc = xb + (size_t)c * HW4 + tid;
        // 4 independent LDG.128 (MLP=4) before any FMA
        const float4 r0 = __ldg(xc);
        const float4 r1 = __ldg(xc + 256);
        const float4 r2 = __ldg(xc + 512);
        float4 r3 = z;
        if (tail) r3 = __ldg(xc + 768);

        a0.x += v * r0.x; a0.y += v * r0.y; a0.z += v * r0.z; a0.w += v * r0.w;
        a1.x += v * r1.x; a1.y += v * r1.y; a1.z += v * r1.z; a1.w += v * r1.w;
        a2.x += v * r2.x; a2.y += v * r2.y; a2.z += v * r2.z; a2.w += v * r2.w;
        if (tail) {
            a3.x += v * r3.x; a3.y += v * r3.y; a3.z += v * r3.z; a3.w += v * r3.w;
        }
    }

    // streaming stores: evict-first so the write stream doesn't evict x in L2
    float4* ob = out + (size_t)bo * HW4 + tid;
    __stcs(ob,       a0);
    __stcs(ob + 256, a1);
    __stcs(ob + 512, a2);
    if (tail) __stcs(ob + 768, a3);
}

extern "C" void kernel_launch(void* const* d_in, const int* in_sizes, int n_in,
                              void* d_out, int out_size) {
    const float4* x = (const float4*)d_in[0];
    const float*  w = (const float*)d_in[1];
    float4* out = (float4*)d_out;

    prune_fused<<<NPLANE, 256>>>(x, w, out);
}